// round 4
// baseline (speedup 1.0000x reference)
#include <cuda_runtime.h>
#include <stdint.h>
#include <math.h>

// Problem constants
#define BB 4
#define SS 2048
#define DD 1024
#define HH 16
#define DK 64
#define MM (BB * SS)                  // 8192 rows for projections
#define OUT0 ((size_t)BB * SS * DD)   // offset of attn in d_out (elements)

// Scratch (device globals)
__device__ __align__(16) float g_Qp[MM * DD];
__device__ __align__(16) float g_Kp[MM * DD];
__device__ __align__(16) float g_Vp[MM * DD];
__device__ __align__(16) float g_Xp[MM * DD];
__device__ float g_rinv[(size_t)BB * HH * SS];

// ---------------------------------------------------------------------------
// tf32x3 helpers
// ---------------------------------------------------------------------------
__device__ __forceinline__ uint32_t f2tf(float x) {
    uint32_t r;
    asm("cvt.rna.tf32.f32 %0, %1;" : "=r"(r) : "f"(x));
    return r;
}
__device__ __forceinline__ void split2u(float x, uint32_t& hu, uint32_t& lu) {
    hu = f2tf(x);
    lu = f2tf(x - __uint_as_float(hu));
}
__device__ __forceinline__ void mma8(float* c,
                                     uint32_t a0, uint32_t a1, uint32_t a2, uint32_t a3,
                                     uint32_t b0, uint32_t b1) {
    asm volatile(
        "mma.sync.aligned.m16n8k8.row.col.f32.tf32.tf32.f32 "
        "{%0,%1,%2,%3}, {%4,%5,%6,%7}, {%8,%9}, {%0,%1,%2,%3};"
        : "+f"(c[0]), "+f"(c[1]), "+f"(c[2]), "+f"(c[3])
        : "r"(a0), "r"(a1), "r"(a2), "r"(a3), "r"(b0), "r"(b1));
}
__device__ __forceinline__ void cpasync16(void* smem, const void* gmem) {
    uint32_t sa = (uint32_t)__cvta_generic_to_shared(smem);
    asm volatile("cp.async.cg.shared.global [%0], [%1], 16;" :: "r"(sa), "l"(gmem));
}

// ---------------------------------------------------------------------------
// SGEMM (tensor core tf32x3, fp32 smem + in-reg split, cp.async 2-stage):
// C[M,N] = A[M,K] @ W^T + bias, W row-major [N,K].
// Block 128x128, BK=16, 256 threads = 8 warps (2x4), warp tile 64x32.
// ---------------------------------------------------------------------------
__global__ __launch_bounds__(256, 2) void gemm_nt_tc2(
    const float* __restrict__ A, const float* __restrict__ W,
    const float* __restrict__ bias, float* __restrict__ C,
    int K, int N)
{
    __shared__ float As[2][128][20];
    __shared__ float Bs[2][128][20];

    const int bm = blockIdx.y * 128, bn = blockIdx.x * 128;
    const int tid = threadIdx.x, lane = tid & 31, warp = tid >> 5;
    const int wm = (warp >> 2) * 64, wn = (warp & 3) * 32;
    const int g = lane >> 2, tg = lane & 3;

    const int lrow0 = tid >> 2, lkk = (tid & 3) * 4;
    const int lrow1 = lrow0 + 64;
    const float* a0p = A + (size_t)(bm + lrow0) * K + lkk;
    const float* a1p = A + (size_t)(bm + lrow1) * K + lkk;
    const float* b0p = W + (size_t)(bn + lrow0) * K + lkk;
    const float* b1p = W + (size_t)(bn + lrow1) * K + lkk;

    float acc[4][4][4];
#pragma unroll
    for (int mt = 0; mt < 4; mt++)
#pragma unroll
        for (int nt = 0; nt < 4; nt++)
#pragma unroll
            for (int r = 0; r < 4; r++) acc[mt][nt][r] = 0.f;

    const int nk = K / 16;
    cpasync16(&As[0][lrow0][lkk], a0p);
    cpasync16(&As[0][lrow1][lkk], a1p);
    cpasync16(&Bs[0][lrow0][lkk], b0p);
    cpasync16(&Bs[0][lrow1][lkk], b1p);
    asm volatile("cp.async.commit_group;");

    for (int it = 0; it < nk; it++) {
        const int s = it & 1;
        if (it + 1 < nk) {
            const int k1 = (it + 1) * 16;
            cpasync16(&As[s ^ 1][lrow0][lkk], a0p + k1);
            cpasync16(&As[s ^ 1][lrow1][lkk], a1p + k1);
            cpasync16(&Bs[s ^ 1][lrow0][lkk], b0p + k1);
            cpasync16(&Bs[s ^ 1][lrow1][lkk], b1p + k1);
            asm volatile("cp.async.commit_group;");
            asm volatile("cp.async.wait_group 1;");
        } else {
            asm volatile("cp.async.wait_group 0;");
        }
        __syncthreads();

#pragma unroll
        for (int ks = 0; ks < 2; ks++) {
            const int kb = ks * 8;
            uint32_t bh[4][2], bl[4][2];
#pragma unroll
            for (int nt = 0; nt < 4; nt++) {
                int n = wn + nt * 8 + g;
                split2u(Bs[s][n][kb + tg],     bh[nt][0], bl[nt][0]);
                split2u(Bs[s][n][kb + tg + 4], bh[nt][1], bl[nt][1]);
            }
#pragma unroll
            for (int mt = 0; mt < 4; mt++) {
                int m = wm + mt * 16 + g;
                uint32_t ah[4], al[4];
                split2u(As[s][m][kb + tg],         ah[0], al[0]);
                split2u(As[s][m + 8][kb + tg],     ah[1], al[1]);
                split2u(As[s][m][kb + tg + 4],     ah[2], al[2]);
                split2u(As[s][m + 8][kb + tg + 4], ah[3], al[3]);
#pragma unroll
                for (int nt = 0; nt < 4; nt++) {
                    mma8(acc[mt][nt], ah[0], ah[1], ah[2], ah[3], bh[nt][0], bh[nt][1]);
                    mma8(acc[mt][nt], ah[0], ah[1], ah[2], ah[3], bl[nt][0], bl[nt][1]);
                    mma8(acc[mt][nt], al[0], al[1], al[2], al[3], bh[nt][0], bh[nt][1]);
                }
            }
        }
        __syncthreads();
    }

#pragma unroll
    for (int mt = 0; mt < 4; mt++) {
        int row = bm + wm + mt * 16 + g;
#pragma unroll
        for (int nt = 0; nt < 4; nt++) {
            int col = bn + wn + nt * 8 + tg * 2;
            float b0 = bias[col], b1 = bias[col + 1];
            float2 v0 = make_float2(acc[mt][nt][0] + b0, acc[mt][nt][1] + b1);
            float2 v1 = make_float2(acc[mt][nt][2] + b0, acc[mt][nt][3] + b1);
            *(float2*)(C + (size_t)row * N + col) = v0;
            *(float2*)(C + (size_t)(row + 8) * N + col) = v1;
        }
    }
}

// ---------------------------------------------------------------------------
// Fused attention with pre-split (hi,lo) smem operands.
// smem (floats): Qs[128][68] @0 ; K2 uint2[32][68] @8704 ; V2 uint2[32][68]
// @13056 ; P2 uint2[32 k][132 m] @17408 ; rs[128] @25856. Total 25984 fl.
// ---------------------------------------------------------------------------
#define IT 128
#define JT 32
#define FA_SMEM_BYTES 103936

__global__ __launch_bounds__(256) void fused_attn(float* __restrict__ attn)
{
    extern __shared__ float sm[];
    float* Qs = sm;                          // [128][68] fp32
    uint2* K2 = (uint2*)(sm + 8704);         // [n(j) 32][k(dk) 64 pad 68]
    uint2* V2 = (uint2*)(sm + 13056);        // [k(j) 32][n(d) 64 pad 68]
    uint2* P2 = (uint2*)(sm + 17408);        // [k(j) 32][m 128 pad 132]
    float* rs = sm + 25856;                  // [128]

    const int bh = blockIdx.z, b = bh >> 4, h = bh & 15;
    const int itile = (gridDim.x - 1) - blockIdx.x;   // heavy tiles first
    const int i0 = itile * IT;
    const int tid = threadIdx.x, lane = tid & 31, warp = tid >> 5;
    const int g = lane >> 2, tg = lane & 3;
    const int wm = warp * 16;                               // S-phase rows
    const int wmv = (warp >> 1) * 32, wnv = (warp & 1) * 32; // AV-phase

    // load Q tile [128][64] -> Qs
#pragma unroll
    for (int u = 0; u < 8; u++) {
        int idx = tid + u * 256;
        int row = idx >> 4, c4 = (idx & 15) * 4;
        float4 v = *(const float4*)(g_Qp + (size_t)(b * SS + i0 + row) * DD + h * DK + c4);
        *(float4*)&Qs[row * 68 + c4] = v;
    }

    float acc_v[2][4][4];
#pragma unroll
    for (int mt = 0; mt < 2; mt++)
#pragma unroll
        for (int nt = 0; nt < 4; nt++)
#pragma unroll
            for (int r = 0; r < 4; r++) acc_v[mt][nt][r] = 0.f;
    float rs0 = 0.f, rs1 = 0.f;

    // K/V prefetch assignment: 32 rows x 16 float4 = 512 chunks, 2/thread
    const int krow0 = tid >> 4, kc4 = (tid & 15) * 4;
    const int krow1 = krow0 + 16;

    const int nj = (i0 >> 5) + 4;
    float4 kv[4];
    kv[0] = *(const float4*)(g_Kp + (size_t)(b * SS + krow0) * DD + h * DK + kc4);
    kv[1] = *(const float4*)(g_Kp + (size_t)(b * SS + krow1) * DD + h * DK + kc4);
    kv[2] = *(const float4*)(g_Vp + (size_t)(b * SS + krow0) * DD + h * DK + kc4);
    kv[3] = *(const float4*)(g_Vp + (size_t)(b * SS + krow1) * DD + h * DK + kc4);

    const int m0 = wm + g;
    const int gi0 = i0 + m0, gi1 = gi0 + 8;
    float* arow0 = attn + ((size_t)bh * SS + gi0) * SS;
    float* arow1 = attn + ((size_t)bh * SS + gi1) * SS;

    uint4* K4 = (uint4*)K2;
    uint4* V4 = (uint4*)V2;

    for (int t = 0; t < nj; t++) {
        const int j0 = t * JT;
        __syncthreads();   // prev chunk's K2/V2/P2 fully consumed
        // split-store K/V (each value split exactly once block-wide)
        {
            uint32_t h0, l0, h1, l1, h2, l2, h3, l3;
            split2u(kv[0].x, h0, l0); split2u(kv[0].y, h1, l1);
            split2u(kv[0].z, h2, l2); split2u(kv[0].w, h3, l3);
            K4[krow0 * 34 + (kc4 >> 1)]     = make_uint4(h0, l0, h1, l1);
            K4[krow0 * 34 + (kc4 >> 1) + 1] = make_uint4(h2, l2, h3, l3);
            split2u(kv[1].x, h0, l0); split2u(kv[1].y, h1, l1);
            split2u(kv[1].z, h2, l2); split2u(kv[1].w, h3, l3);
            K4[krow1 * 34 + (kc4 >> 1)]     = make_uint4(h0, l0, h1, l1);
            K4[krow1 * 34 + (kc4 >> 1) + 1] = make_uint4(h2, l2, h3, l3);
            split2u(kv[2].x, h0, l0); split2u(kv[2].y, h1, l1);
            split2u(kv[2].z, h2, l2); split2u(kv[2].w, h3, l3);
            V4[krow0 * 34 + (kc4 >> 1)]     = make_uint4(h0, l0, h1, l1);
            V4[krow0 * 34 + (kc4 >> 1) + 1] = make_uint4(h2, l2, h3, l3);
            split2u(kv[3].x, h0, l0); split2u(kv[3].y, h1, l1);
            split2u(kv[3].z, h2, l2); split2u(kv[3].w, h3, l3);
            V4[krow1 * 34 + (kc4 >> 1)]     = make_uint4(h0, l0, h1, l1);
            V4[krow1 * 34 + (kc4 >> 1) + 1] = make_uint4(h2, l2, h3, l3);
        }
        __syncthreads();
        if (t + 1 < nj) {
            const int j0n = j0 + JT;
            kv[0] = *(const float4*)(g_Kp + (size_t)(b * SS + j0n + krow0) * DD + h * DK + kc4);
            kv[1] = *(const float4*)(g_Kp + (size_t)(b * SS + j0n + krow1) * DD + h * DK + kc4);
            kv[2] = *(const float4*)(g_Vp + (size_t)(b * SS + j0n + krow0) * DD + h * DK + kc4);
            kv[3] = *(const float4*)(g_Vp + (size_t)(b * SS + j0n + krow1) * DD + h * DK + kc4);
        }

        // ---- S = Q.K^T  (warp: 16 rows x 32 cols) ----
        float acc_s[4][4];
#pragma unroll
        for (int nt = 0; nt < 4; nt++)
#pragma unroll
            for (int r = 0; r < 4; r++) acc_s[nt][r] = 0.f;

#pragma unroll
        for (int kb = 0; kb < DK; kb += 8) {
            uint32_t ah[4], al[4];
            split2u(Qs[m0 * 68 + kb + tg],           ah[0], al[0]);
            split2u(Qs[(m0 + 8) * 68 + kb + tg],     ah[1], al[1]);
            split2u(Qs[m0 * 68 + kb + tg + 4],       ah[2], al[2]);
            split2u(Qs[(m0 + 8) * 68 + kb + tg + 4], ah[3], al[3]);
#pragma unroll
            for (int nt = 0; nt < 4; nt++) {
                int n = nt * 8 + g;
                uint2 k0 = K2[n * 68 + kb + tg];
                uint2 k1 = K2[n * 68 + kb + tg + 4];
                mma8(acc_s[nt], ah[0], ah[1], ah[2], ah[3], k0.x, k1.x);
                mma8(acc_s[nt], ah[0], ah[1], ah[2], ah[3], k0.y, k1.y);
                mma8(acc_s[nt], al[0], al[1], al[2], al[3], k0.x, k1.x);
            }
        }

        // ---- exp, mask, rowsum, write attn, split-store P ----
        const bool needmask = (j0 + JT - 1 > gi0);
#pragma unroll
        for (int nt = 0; nt < 4; nt++) {
            int cl = nt * 8 + tg * 2;
            int c = j0 + cl;
            float p00 = __expf(acc_s[nt][0] * 0.125f);
            float p01 = __expf(acc_s[nt][1] * 0.125f);
            float p10 = __expf(acc_s[nt][2] * 0.125f);
            float p11 = __expf(acc_s[nt][3] * 0.125f);
            if (needmask) {
                if (c     > gi0) p00 = 0.f;
                if (c + 1 > gi0) p01 = 0.f;
                if (c     > gi1) p10 = 0.f;
                if (c + 1 > gi1) p11 = 0.f;
            }
            rs0 += p00 + p01;
            rs1 += p10 + p11;
            *(float2*)(arow0 + c) = make_float2(p00, p01);
            *(float2*)(arow1 + c) = make_float2(p10, p11);
            uint32_t hh, ll;
            split2u(p00, hh, ll); P2[cl * 132 + m0]           = make_uint2(hh, ll);
            split2u(p01, hh, ll); P2[(cl + 1) * 132 + m0]     = make_uint2(hh, ll);
            split2u(p10, hh, ll); P2[cl * 132 + m0 + 8]       = make_uint2(hh, ll);
            split2u(p11, hh, ll); P2[(cl + 1) * 132 + m0 + 8] = make_uint2(hh, ll);
        }
        __syncthreads();   // P2 visible to all warps

        // ---- X_acc += P @ V  (warp: 32 rows x 32 cols) ----
#pragma unroll
        for (int kb = 0; kb < JT; kb += 8) {
            uint2 pa[2][4];
#pragma unroll
            for (int mt = 0; mt < 2; mt++) {
                int m = wmv + mt * 16 + g;
                pa[mt][0] = P2[(kb + tg) * 132 + m];
                pa[mt][1] = P2[(kb + tg) * 132 + m + 8];
                pa[mt][2] = P2[(kb + tg + 4) * 132 + m];
                pa[mt][3] = P2[(kb + tg + 4) * 132 + m + 8];
            }
#pragma unroll
            for (int nt = 0; nt < 4; nt++) {
                int n = wnv + nt * 8 + g;
                uint2 v0 = V2[(kb + tg) * 68 + n];
                uint2 v1 = V2[(kb + tg + 4) * 68 + n];
#pragma unroll
                for (int mt = 0; mt < 2; mt++) {
                    mma8(acc_v[mt][nt], pa[mt][0].x, pa[mt][1].x, pa[mt][2].x, pa[mt][3].x, v0.x, v1.x);
                    mma8(acc_v[mt][nt], pa[mt][0].x, pa[mt][1].x, pa[mt][2].x, pa[mt][3].x, v0.y, v1.y);
                    mma8(acc_v[mt][nt], pa[mt][0].y, pa[mt][1].y, pa[mt][2].y, pa[mt][3].y, v0.x, v1.x);
                }
            }
        }
    }

    // ---- rowsum reduce + write inv ----
    rs0 += __shfl_xor_sync(0xffffffffu, rs0, 1);
    rs0 += __shfl_xor_sync(0xffffffffu, rs0, 2);
    rs1 += __shfl_xor_sync(0xffffffffu, rs1, 1);
    rs1 += __shfl_xor_sync(0xffffffffu, rs1, 2);
    if (tg == 0) { rs[m0] = rs0; rs[m0 + 8] = rs1; }
    __syncthreads();
    if (tid < 128) g_rinv[(size_t)bh * SS + i0 + tid] = 1.0f / rs[tid];

    // ---- X = X_acc / rowsum ----
#pragma unroll
    for (int mt = 0; mt < 2; mt++) {
        int r0 = wmv + mt * 16 + g, r1 = r0 + 8;
        float inv0 = 1.0f / rs[r0], inv1 = 1.0f / rs[r1];
        float* x0 = g_Xp + (size_t)(b * SS + i0 + r0) * DD + h * DK;
        float* x1 = g_Xp + (size_t)(b * SS + i0 + r1) * DD + h * DK;
#pragma unroll
        for (int nt = 0; nt < 4; nt++) {
            int cc = wnv + nt * 8 + tg * 2;
            *(float2*)(x0 + cc) = make_float2(acc_v[mt][nt][0] * inv0, acc_v[mt][nt][1] * inv0);
            *(float2*)(x1 + cc) = make_float2(acc_v[mt][nt][2] * inv1, acc_v[mt][nt][3] * inv1);
        }
    }

    // ---- zero-fill strictly-upper tiles (d_out is poisoned) ----
    const int jend = i0 + IT;
    const int zw4 = (SS - jend) >> 2;
    if (zw4 > 0) {
        float4 z = make_float4(0.f, 0.f, 0.f, 0.f);
        for (int r = warp; r < IT; r += 8) {
            float* rowp = attn + ((size_t)bh * SS + i0 + r) * SS + jend;
            for (int cq = lane; cq < zw4; cq += 32)
                *(float4*)(rowp + cq * 4) = z;
        }
    }
}

// ---------------------------------------------------------------------------
// Normalize attn rows: p[0..i] *= 1/rowsum. One block per row.
// ---------------------------------------------------------------------------
__global__ __launch_bounds__(256) void normalize_attn(float* __restrict__ attn)
{
    const int row = blockIdx.x;
    const int i = row & (SS - 1);
    const float inv = g_rinv[row];
    float* p = attn + (size_t)row * SS;
    const int L = i + 1;
    const int n4 = L >> 2;
    for (int q = threadIdx.x; q < n4; q += 256) {
        float4 v = ((float4*)p)[q];
        v.x *= inv; v.y *= inv; v.z *= inv; v.w *= inv;
        ((float4*)p)[q] = v;
    }
    for (int q = (n4 << 2) + threadIdx.x; q < L; q += 256) p[q] *= inv;
}

// ---------------------------------------------------------------------------
extern "C" void kernel_launch(void* const* d_in, const int* in_sizes, int n_in,
                              void* d_out, int out_size)
{
    const float* q    = (const float*)d_in[0];
    const float* k    = (const float*)d_in[1];
    const float* v    = (const float*)d_in[2];
    // d_in[3] = mask (tril) — causality applied analytically
    const float* wq_w = (const float*)d_in[4];
    const float* wq_b = (const float*)d_in[5];
    const float* wk_w = (const float*)d_in[6];
    const float* wk_b = (const float*)d_in[7];
    const float* wv_w = (const float*)d_in[8];
    const float* wv_b = (const float*)d_in[9];
    const float* wo_w = (const float*)d_in[10];
    const float* wo_b = (const float*)d_in[11];

    float* out  = (float*)d_out;
    float* attn = (float*)d_out + OUT0;

    float *qp, *kp, *vp, *xp;
    cudaGetSymbolAddress((void**)&qp, g_Qp);
    cudaGetSymbolAddress((void**)&kp, g_Kp);
    cudaGetSymbolAddress((void**)&vp, g_Vp);
    cudaGetSymbolAddress((void**)&xp, g_Xp);

    static bool attr_set = false;
    if (!attr_set) {
        cudaFuncSetAttribute(fused_attn, cudaFuncAttributeMaxDynamicSharedMemorySize,
                             FA_SMEM_BYTES);
        attr_set = true;
    }

    dim3 gproj(DD / 128, MM / 128);        // (8, 64)
    gemm_nt_tc2<<<gproj, 256>>>(q, wq_w, wq_b, qp, DD, DD);
    gemm_nt_tc2<<<gproj, 256>>>(k, wk_w, wk_b, kp, DD, DD);
    gemm_nt_tc2<<<gproj, 256>>>(v, wv_w, wv_b, vp, DD, DD);

    dim3 gfa(SS / IT, 1, BB * HH);         // (16, 1, 64)
    fused_attn<<<gfa, 256, FA_SMEM_BYTES>>>(attn);

    normalize_attn<<<BB * HH * SS, 256>>>(attn);

    gemm_nt_tc2<<<gproj, 256>>>(xp, wo_w, wo_b, out, DD, DD);
}

// round 5
// speedup vs baseline: 1.7202x; 1.7202x over previous
#include <cuda_runtime.h>
#include <stdint.h>
#include <math.h>

// Problem constants
#define BB 4
#define SS 2048
#define DD 1024
#define HH 16
#define DK 64
#define MM (BB * SS)                  // 8192 rows for projections
#define OUT0 ((size_t)BB * SS * DD)   // offset of attn in d_out (elements)

// Scratch (device globals)
__device__ __align__(16) float g_Qp[MM * DD];
__device__ __align__(16) float g_Kp[MM * DD];
__device__ __align__(16) float g_Vp[MM * DD];
__device__ __align__(16) float g_Xp[MM * DD];
__device__ float g_rinv[(size_t)BB * HH * SS];

// ---------------------------------------------------------------------------
// bf16x3 helpers. bfsplit2: pack (x0,x1) -> hi bf16x2 reg + lo bf16x2 reg.
// Packed reg layout: bits[15:0] = element k, bits[31:16] = element k+1.
// ---------------------------------------------------------------------------
__device__ __forceinline__ void bfsplit2(float x0, float x1,
                                         uint32_t& hi, uint32_t& lo) {
    asm("cvt.rn.bf16x2.f32 %0, %1, %2;" : "=r"(hi) : "f"(x1), "f"(x0));
    float h0 = __uint_as_float(hi << 16);
    float h1 = __uint_as_float(hi & 0xffff0000u);
    asm("cvt.rn.bf16x2.f32 %0, %1, %2;" : "=r"(lo) : "f"(x1 - h1), "f"(x0 - h0));
}
__device__ __forceinline__ void mma16(float* c,
                                      uint32_t a0, uint32_t a1, uint32_t a2, uint32_t a3,
                                      uint32_t b0, uint32_t b1) {
    asm volatile(
        "mma.sync.aligned.m16n8k16.row.col.f32.bf16.bf16.f32 "
        "{%0,%1,%2,%3}, {%4,%5,%6,%7}, {%8,%9}, {%0,%1,%2,%3};"
        : "+f"(c[0]), "+f"(c[1]), "+f"(c[2]), "+f"(c[3])
        : "r"(a0), "r"(a1), "r"(a2), "r"(a3), "r"(b0), "r"(b1));
}
__device__ __forceinline__ void cpasync16(void* smem, const void* gmem) {
    uint32_t sa = (uint32_t)__cvta_generic_to_shared(smem);
    asm volatile("cp.async.cg.shared.global [%0], [%1], 16;" :: "r"(sa), "l"(gmem));
}

// ---------------------------------------------------------------------------
// SGEMM (bf16x3, fp32 smem + in-reg split, cp.async 2-stage):
// C[M,N] = A[M,K] @ W^T + bias, W row-major [N,K].
// Block 128x128, BK=16, 256 threads = 8 warps (2x4), warp tile 64x32.
// Dynamic smem: As[2][128][24] + Bs[2][128][24] fp32 = 49152 B.
// ---------------------------------------------------------------------------
#define GLD 24
#define GEMM_SMEM_BYTES (2 * 2 * 128 * GLD * 4)

__global__ __launch_bounds__(256, 2) void gemm_nt_tc3(
    const float* __restrict__ A, const float* __restrict__ W,
    const float* __restrict__ bias, float* __restrict__ C,
    int K, int N)
{
    extern __shared__ float gsm[];
    float* As = gsm;                       // [2][128][24]
    float* Bs = gsm + 2 * 128 * GLD;       // [2][128][24]

    const int bm = blockIdx.y * 128, bn = blockIdx.x * 128;
    const int tid = threadIdx.x, lane = tid & 31, warp = tid >> 5;
    const int wm = (warp >> 2) * 64, wn = (warp & 3) * 32;
    const int g = lane >> 2, tg = lane & 3;

    const int lrow0 = tid >> 2, lkk = (tid & 3) * 4;
    const int lrow1 = lrow0 + 64;
    const float* a0p = A + (size_t)(bm + lrow0) * K + lkk;
    const float* a1p = A + (size_t)(bm + lrow1) * K + lkk;
    const float* b0p = W + (size_t)(bn + lrow0) * K + lkk;
    const float* b1p = W + (size_t)(bn + lrow1) * K + lkk;

    float acc[4][4][4];
#pragma unroll
    for (int mt = 0; mt < 4; mt++)
#pragma unroll
        for (int nt = 0; nt < 4; nt++)
#pragma unroll
            for (int r = 0; r < 4; r++) acc[mt][nt][r] = 0.f;

    const int nk = K / 16;
    cpasync16(&As[0 * 128 * GLD + lrow0 * GLD + lkk], a0p);
    cpasync16(&As[0 * 128 * GLD + lrow1 * GLD + lkk], a1p);
    cpasync16(&Bs[0 * 128 * GLD + lrow0 * GLD + lkk], b0p);
    cpasync16(&Bs[0 * 128 * GLD + lrow1 * GLD + lkk], b1p);
    asm volatile("cp.async.commit_group;");

    for (int it = 0; it < nk; it++) {
        const int s = it & 1;
        if (it + 1 < nk) {
            const int k1 = (it + 1) * 16;
            const int so = (s ^ 1) * 128 * GLD;
            cpasync16(&As[so + lrow0 * GLD + lkk], a0p + k1);
            cpasync16(&As[so + lrow1 * GLD + lkk], a1p + k1);
            cpasync16(&Bs[so + lrow0 * GLD + lkk], b0p + k1);
            cpasync16(&Bs[so + lrow1 * GLD + lkk], b1p + k1);
            asm volatile("cp.async.commit_group;");
            asm volatile("cp.async.wait_group 1;");
        } else {
            asm volatile("cp.async.wait_group 0;");
        }
        __syncthreads();

        const float* Ab = As + s * 128 * GLD;
        const float* Bb = Bs + s * 128 * GLD;
        uint32_t bh[4][2], bl[4][2];
#pragma unroll
        for (int nt = 0; nt < 4; nt++) {
            int n = wn + nt * 8 + g;
            float2 p0 = *(const float2*)&Bb[n * GLD + 2 * tg];
            float2 p1 = *(const float2*)&Bb[n * GLD + 2 * tg + 8];
            bfsplit2(p0.x, p0.y, bh[nt][0], bl[nt][0]);
            bfsplit2(p1.x, p1.y, bh[nt][1], bl[nt][1]);
        }
#pragma unroll
        for (int mt = 0; mt < 4; mt++) {
            int m = wm + mt * 16 + g;
            float2 q0 = *(const float2*)&Ab[m * GLD + 2 * tg];
            float2 q1 = *(const float2*)&Ab[(m + 8) * GLD + 2 * tg];
            float2 q2 = *(const float2*)&Ab[m * GLD + 2 * tg + 8];
            float2 q3 = *(const float2*)&Ab[(m + 8) * GLD + 2 * tg + 8];
            uint32_t ah[4], al[4];
            bfsplit2(q0.x, q0.y, ah[0], al[0]);
            bfsplit2(q1.x, q1.y, ah[1], al[1]);
            bfsplit2(q2.x, q2.y, ah[2], al[2]);
            bfsplit2(q3.x, q3.y, ah[3], al[3]);
#pragma unroll
            for (int nt = 0; nt < 4; nt++) {
                mma16(acc[mt][nt], ah[0], ah[1], ah[2], ah[3], bh[nt][0], bh[nt][1]);
                mma16(acc[mt][nt], ah[0], ah[1], ah[2], ah[3], bl[nt][0], bl[nt][1]);
                mma16(acc[mt][nt], al[0], al[1], al[2], al[3], bh[nt][0], bh[nt][1]);
            }
        }
        __syncthreads();
    }

#pragma unroll
    for (int mt = 0; mt < 4; mt++) {
        int row = bm + wm + mt * 16 + g;
#pragma unroll
        for (int nt = 0; nt < 4; nt++) {
            int col = bn + wn + nt * 8 + tg * 2;
            float b0 = bias[col], b1 = bias[col + 1];
            float2 v0 = make_float2(acc[mt][nt][0] + b0, acc[mt][nt][1] + b1);
            float2 v1 = make_float2(acc[mt][nt][2] + b0, acc[mt][nt][3] + b1);
            *(float2*)(C + (size_t)row * N + col) = v0;
            *(float2*)(C + (size_t)(row + 8) * N + col) = v1;
        }
    }
}

// ---------------------------------------------------------------------------
// Fused attention, bf16x3 with pre-split packed operands (bf16x2 = fp32 bytes).
// smem (uint32 words):
//   Qh[128][36] @0      Ql @4608     (Q split once per tile)
//   Kh[32][36]  @9216   Kl @10368    (split at chunk load)
//   Vs fp32[32][68] @11520           (staging for transpose-split)
//   Vh[64][20] @13696   Vl @14976    ([d][jpair], packed along j)
//   Ph[128][20] @16256  Pl @18816    ([m][jpair], packed along j)
//   rs fp32[128] @21376
// total 21504 words = 86016 B
// ---------------------------------------------------------------------------
#define IT 128
#define JT 32
#define FA_SMEM_BYTES 86016

__global__ __launch_bounds__(256) void fused_attn(float* __restrict__ attn)
{
    extern __shared__ uint32_t smu[];
    uint32_t* Qh = smu;
    uint32_t* Ql = smu + 4608;
    uint32_t* Kh = smu + 9216;
    uint32_t* Kl = smu + 10368;
    float*    Vs = (float*)(smu + 11520);
    uint32_t* Vh = smu + 13696;
    uint32_t* Vl = smu + 14976;
    uint32_t* Ph = smu + 16256;
    uint32_t* Pl = smu + 18816;
    float*    rs = (float*)(smu + 21376);

    const int bh = blockIdx.z, b = bh >> 4, h = bh & 15;
    const int itile = (gridDim.x - 1) - blockIdx.x;   // heavy tiles first
    const int i0 = itile * IT;
    const int tid = threadIdx.x, lane = tid & 31, warp = tid >> 5;
    const int g = lane >> 2, tg = lane & 3;
    const int wm = warp * 16;                                // S-phase rows
    const int wmv = (warp >> 1) * 32, wnv = (warp & 1) * 32; // AV-phase

    // ---- load + split Q tile once: [128][64] -> Qh/Ql packed pairs ----
#pragma unroll
    for (int u = 0; u < 8; u++) {
        int idx = tid + u * 256;
        int row = idx >> 4, c4 = (idx & 15) * 4;
        float4 v = *(const float4*)(g_Qp + (size_t)(b * SS + i0 + row) * DD + h * DK + c4);
        uint32_t h0, l0, h1, l1;
        bfsplit2(v.x, v.y, h0, l0);
        bfsplit2(v.z, v.w, h1, l1);
        *(uint2*)&Qh[row * 36 + (c4 >> 1)] = make_uint2(h0, h1);
        *(uint2*)&Ql[row * 36 + (c4 >> 1)] = make_uint2(l0, l1);
    }

    float acc_v[2][4][4];
#pragma unroll
    for (int mt = 0; mt < 2; mt++)
#pragma unroll
        for (int nt = 0; nt < 4; nt++)
#pragma unroll
            for (int r = 0; r < 4; r++) acc_v[mt][nt][r] = 0.f;
    float rs0 = 0.f, rs1 = 0.f;

    // K/V prefetch assignment: 32 rows x 16 float4 = 512 chunks, 2/thread
    const int krow0 = tid >> 4, kc4 = (tid & 15) * 4;
    const int krow1 = krow0 + 16;

    const int nj = (i0 >> 5) + 4;
    float4 kv[4];
    kv[0] = *(const float4*)(g_Kp + (size_t)(b * SS + krow0) * DD + h * DK + kc4);
    kv[1] = *(const float4*)(g_Kp + (size_t)(b * SS + krow1) * DD + h * DK + kc4);
    kv[2] = *(const float4*)(g_Vp + (size_t)(b * SS + krow0) * DD + h * DK + kc4);
    kv[3] = *(const float4*)(g_Vp + (size_t)(b * SS + krow1) * DD + h * DK + kc4);

    const int m0 = wm + g;
    const int gi0 = i0 + m0, gi1 = gi0 + 8;
    float* arow0 = attn + ((size_t)bh * SS + gi0) * SS;
    float* arow1 = attn + ((size_t)bh * SS + gi1) * SS;

    for (int t = 0; t < nj; t++) {
        const int j0 = t * JT;
        __syncthreads();   // prev chunk's Kh/Vs/Ph/Vh fully consumed
        {   // K split-store + V fp32 staging
            uint32_t h0, l0, h1, l1;
            bfsplit2(kv[0].x, kv[0].y, h0, l0);
            bfsplit2(kv[0].z, kv[0].w, h1, l1);
            *(uint2*)&Kh[krow0 * 36 + (kc4 >> 1)] = make_uint2(h0, h1);
            *(uint2*)&Kl[krow0 * 36 + (kc4 >> 1)] = make_uint2(l0, l1);
            bfsplit2(kv[1].x, kv[1].y, h0, l0);
            bfsplit2(kv[1].z, kv[1].w, h1, l1);
            *(uint2*)&Kh[krow1 * 36 + (kc4 >> 1)] = make_uint2(h0, h1);
            *(uint2*)&Kl[krow1 * 36 + (kc4 >> 1)] = make_uint2(l0, l1);
            *(float4*)&Vs[krow0 * 68 + kc4] = kv[2];
            *(float4*)&Vs[krow1 * 68 + kc4] = kv[3];
        }
        __syncthreads();
        if (t + 1 < nj) {
            const int j0n = j0 + JT;
            kv[0] = *(const float4*)(g_Kp + (size_t)(b * SS + j0n + krow0) * DD + h * DK + kc4);
            kv[1] = *(const float4*)(g_Kp + (size_t)(b * SS + j0n + krow1) * DD + h * DK + kc4);
            kv[2] = *(const float4*)(g_Vp + (size_t)(b * SS + j0n + krow0) * DD + h * DK + kc4);
            kv[3] = *(const float4*)(g_Vp + (size_t)(b * SS + j0n + krow1) * DD + h * DK + kc4);
        }

        // ---- V transpose-split: Vs[j][d] -> Vh/Vl [d][jpair] ----
        {
            int n = tid >> 2;
            int jp0 = tid & 3;
#pragma unroll
            for (int e = 0; e < 4; e++) {
                int jp = jp0 + e * 4;
                float v0 = Vs[(2 * jp) * 68 + n];
                float v1 = Vs[(2 * jp + 1) * 68 + n];
                uint32_t hh, ll;
                bfsplit2(v0, v1, hh, ll);
                Vh[n * 20 + jp] = hh;
                Vl[n * 20 + jp] = ll;
            }
        }

        // ---- S = Q.K^T  (warp: 16 rows x 32 cols), bf16x3 k16 ----
        float acc_s[4][4];
#pragma unroll
        for (int nt = 0; nt < 4; nt++)
#pragma unroll
            for (int r = 0; r < 4; r++) acc_s[nt][r] = 0.f;

#pragma unroll
        for (int s4 = 0; s4 < 4; s4++) {
            const int kb = s4 * 8;   // kpair base
            uint32_t ah[4], al[4];
            ah[0] = Qh[m0 * 36 + kb + tg];           al[0] = Ql[m0 * 36 + kb + tg];
            ah[1] = Qh[(m0 + 8) * 36 + kb + tg];     al[1] = Ql[(m0 + 8) * 36 + kb + tg];
            ah[2] = Qh[m0 * 36 + kb + tg + 4];       al[2] = Ql[m0 * 36 + kb + tg + 4];
            ah[3] = Qh[(m0 + 8) * 36 + kb + tg + 4]; al[3] = Ql[(m0 + 8) * 36 + kb + tg + 4];
#pragma unroll
            for (int nt = 0; nt < 4; nt++) {
                int n = nt * 8 + g;
                uint32_t bh0 = Kh[n * 36 + kb + tg];
                uint32_t bh1 = Kh[n * 36 + kb + tg + 4];
                uint32_t bl0 = Kl[n * 36 + kb + tg];
                uint32_t bl1 = Kl[n * 36 + kb + tg + 4];
                mma16(acc_s[nt], ah[0], ah[1], ah[2], ah[3], bh0, bh1);
                mma16(acc_s[nt], ah[0], ah[1], ah[2], ah[3], bl0, bl1);
                mma16(acc_s[nt], al[0], al[1], al[2], al[3], bh0, bh1);
            }
        }

        // ---- exp, mask, rowsum, write attn, split-pack P ----
        const bool needmask = (j0 + JT - 1 > gi0);
#pragma unroll
        for (int nt = 0; nt < 4; nt++) {
            int cl = nt * 8 + tg * 2;
            int c = j0 + cl;
            float p00 = __expf(acc_s[nt][0] * 0.125f);
            float p01 = __expf(acc_s[nt][1] * 0.125f);
            float p10 = __expf(acc_s[nt][2] * 0.125f);
            float p11 = __expf(acc_s[nt][3] * 0.125f);
            if (needmask) {
                if (c     > gi0) p00 = 0.f;
                if (c + 1 > gi0) p01 = 0.f;
                if (c     > gi1) p10 = 0.f;
                if (c + 1 > gi1) p11 = 0.f;
            }
            rs0 += p00 + p01;
            rs1 += p10 + p11;
            *(float2*)(arow0 + c) = make_float2(p00, p01);
            *(float2*)(arow1 + c) = make_float2(p10, p11);
            uint32_t hh, ll;
            bfsplit2(p00, p01, hh, ll);
            Ph[m0 * 20 + nt * 4 + tg] = hh;
            Pl[m0 * 20 + nt * 4 + tg] = ll;
            bfsplit2(p10, p11, hh, ll);
            Ph[(m0 + 8) * 20 + nt * 4 + tg] = hh;
            Pl[(m0 + 8) * 20 + nt * 4 + tg] = ll;
        }
        __syncthreads();   // Ph/Pl/Vh/Vl visible to all warps

        // ---- X_acc += P @ V  (warp: 32 rows x 32 cols), bf16x3 k16 ----
#pragma unroll
        for (int s2 = 0; s2 < 2; s2++) {
            const int kb = s2 * 8;   // jpair base
            uint32_t pah[2][4], pal[2][4];
#pragma unroll
            for (int mt = 0; mt < 2; mt++) {
                int m = wmv + mt * 16 + g;
                pah[mt][0] = Ph[m * 20 + kb + tg];
                pah[mt][1] = Ph[(m + 8) * 20 + kb + tg];
                pah[mt][2] = Ph[m * 20 + kb + tg + 4];
                pah[mt][3] = Ph[(m + 8) * 20 + kb + tg + 4];
                pal[mt][0] = Pl[m * 20 + kb + tg];
                pal[mt][1] = Pl[(m + 8) * 20 + kb + tg];
                pal[mt][2] = Pl[m * 20 + kb + tg + 4];
                pal[mt][3] = Pl[(m + 8) * 20 + kb + tg + 4];
            }
#pragma unroll
            for (int nt = 0; nt < 4; nt++) {
                int n = wnv + nt * 8 + g;
                uint32_t vh0 = Vh[n * 20 + kb + tg];
                uint32_t vh1 = Vh[n * 20 + kb + tg + 4];
                uint32_t vl0 = Vl[n * 20 + kb + tg];
                uint32_t vl1 = Vl[n * 20 + kb + tg + 4];
#pragma unroll
                for (int mt = 0; mt < 2; mt++) {
                    mma16(acc_v[mt][nt], pah[mt][0], pah[mt][1], pah[mt][2], pah[mt][3], vh0, vh1);
                    mma16(acc_v[mt][nt], pah[mt][0], pah[mt][1], pah[mt][2], pah[mt][3], vl0, vl1);
                    mma16(acc_v[mt][nt], pal[mt][0], pal[mt][1], pal[mt][2], pal[mt][3], vh0, vh1);
                }
            }
        }
    }

    // ---- rowsum reduce + write inv ----
    rs0 += __shfl_xor_sync(0xffffffffu, rs0, 1);
    rs0 += __shfl_xor_sync(0xffffffffu, rs0, 2);
    rs1 += __shfl_xor_sync(0xffffffffu, rs1, 1);
    rs1 += __shfl_xor_sync(0xffffffffu, rs1, 2);
    if (tg == 0) { rs[m0] = rs0; rs[m0 + 8] = rs1; }
    __syncthreads();
    if (tid < 128) g_rinv[(size_t)bh * SS + i0 + tid] = 1.0f / rs[tid];

    // ---- X = X_acc / rowsum ----
#pragma unroll
    for (int mt = 0; mt < 2; mt++) {
        int r0 = wmv + mt * 16 + g, r1 = r0 + 8;
        float inv0 = 1.0f / rs[r0], inv1 = 1.0f / rs[r1];
        float* x0 = g_Xp + (size_t)(b * SS + i0 + r0) * DD + h * DK;
        float* x1 = g_Xp + (size_t)(b * SS + i0 + r1) * DD + h * DK;
#pragma unroll
        for (int nt = 0; nt < 4; nt++) {
            int cc = wnv + nt * 8 + tg * 2;
            *(float2*)(x0 + cc) = make_float2(acc_v[mt][nt][0] * inv0, acc_v[mt][nt][1] * inv0);
            *(float2*)(x1 + cc) = make_float2(acc_v[mt][nt][2] * inv1, acc_v[mt][nt][3] * inv1);
        }
    }

    // ---- zero-fill strictly-upper tiles (d_out is poisoned) ----
    const int jend = i0 + IT;
    const int zw4 = (SS - jend) >> 2;
    if (zw4 > 0) {
        float4 z = make_float4(0.f, 0.f, 0.f, 0.f);
        for (int r = warp; r < IT; r += 8) {
            float* rowp = attn + ((size_t)bh * SS + i0 + r) * SS + jend;
            for (int cq = lane; cq < zw4; cq += 32)
                *(float4*)(rowp + cq * 4) = z;
        }
    }
}

// ---------------------------------------------------------------------------
// Normalize attn rows: p[0..i] *= 1/rowsum. One block per row.
// ---------------------------------------------------------------------------
__global__ __launch_bounds__(256) void normalize_attn(float* __restrict__ attn)
{
    const int row = blockIdx.x;
    const int i = row & (SS - 1);
    const float inv = g_rinv[row];
    float* p = attn + (size_t)row * SS;
    const int L = i + 1;
    const int n4 = L >> 2;
    for (int q = threadIdx.x; q < n4; q += 256) {
        float4 v = ((float4*)p)[q];
        v.x *= inv; v.y *= inv; v.z *= inv; v.w *= inv;
        ((float4*)p)[q] = v;
    }
    for (int q = (n4 << 2) + threadIdx.x; q < L; q += 256) p[q] *= inv;
}

// ---------------------------------------------------------------------------
extern "C" void kernel_launch(void* const* d_in, const int* in_sizes, int n_in,
                              void* d_out, int out_size)
{
    const float* q    = (const float*)d_in[0];
    const float* k    = (const float*)d_in[1];
    const float* v    = (const float*)d_in[2];
    // d_in[3] = mask (tril) — causality applied analytically
    const float* wq_w = (const float*)d_in[4];
    const float* wq_b = (const float*)d_in[5];
    const float* wk_w = (const float*)d_in[6];
    const float* wk_b = (const float*)d_in[7];
    const float* wv_w = (const float*)d_in[8];
    const float* wv_b = (const float*)d_in[9];
    const float* wo_w = (const float*)d_in[10];
    const float* wo_b = (const float*)d_in[11];

    float* out  = (float*)d_out;
    float* attn = (float*)d_out + OUT0;

    float *qp, *kp, *vp, *xp;
    cudaGetSymbolAddress((void**)&qp, g_Qp);
    cudaGetSymbolAddress((void**)&kp, g_Kp);
    cudaGetSymbolAddress((void**)&vp, g_Vp);
    cudaGetSymbolAddress((void**)&xp, g_Xp);

    static bool attr_set = false;
    if (!attr_set) {
        cudaFuncSetAttribute(fused_attn, cudaFuncAttributeMaxDynamicSharedMemorySize,
                             FA_SMEM_BYTES);
        cudaFuncSetAttribute(gemm_nt_tc3, cudaFuncAttributeMaxDynamicSharedMemorySize,
                             GEMM_SMEM_BYTES);
        attr_set = true;
    }

    dim3 gproj(DD / 128, MM / 128);        // (8, 64)
    gemm_nt_tc3<<<gproj, 256, GEMM_SMEM_BYTES>>>(q, wq_w, wq_b, qp, DD, DD);
    gemm_nt_tc3<<<gproj, 256, GEMM_SMEM_BYTES>>>(k, wk_w, wk_b, kp, DD, DD);
    gemm_nt_tc3<<<gproj, 256, GEMM_SMEM_BYTES>>>(v, wv_w, wv_b, vp, DD, DD);

    dim3 gfa(SS / IT, 1, BB * HH);         // (16, 1, 64)
    fused_attn<<<gfa, 256, FA_SMEM_BYTES>>>(attn);

    normalize_attn<<<BB * HH * SS, 256>>>(attn);

    gemm_nt_tc3<<<gproj, 256, GEMM_SMEM_BYTES>>>(xp, wo_w, wo_b, out, DD, DD);
}